// round 10
// baseline (speedup 1.0000x reference)
#include <cuda_runtime.h>
#include <stdint.h>

// Real spherical harmonics up to L=8. Output = concat of 9 parts; part l at
// element offset N*l*l, row i at i*(2l+1), column (l+m), m=-l..l.
//
// T=256, 80 KB dynamic smem (2 CTA/SM). Two-phase pipeline:
//   phase 1: compute+stage l=1..5 -> barrier -> issue their copies (async)
//   phase 2: compute+stage l=6..8 (disjoint smem) -> barrier -> copy l=8..6
// Phase-1 stores drain underneath phase-2 compute (intra-CTA overlap) in
// addition to the 2-CTA/SM cross-CTA phase ping-pong.
// l=0 stored direct (stride-1).

static constexpr double PI_D = 3.141592653589793238462643383279502884;

constexpr double csqrt(double x) {
    double g = (x > 1.0) ? x : 1.0;
    for (int i = 0; i < 200; ++i) g = 0.5 * (g + x / g);
    return g;
}
constexpr double cfact(int n) {
    double r = 1.0;
    for (int i = 2; i <= n; ++i) r *= (double)i;
    return r;
}

struct NormTab { float v[45]; };
constexpr NormTab make_norms() {
    NormTab t{};
    for (int l = 0; l <= 8; ++l)
        for (int m = 0; m <= l; ++m) {
            double n = csqrt((2.0 * l + 1.0) / (4.0 * PI_D) * cfact(l - m) / cfact(l + m));
            if (m > 0) n *= csqrt(2.0);
            t.v[l * (l + 1) / 2 + m] = (float)n;
        }
    return t;
}
__constant__ NormTab g_norm = make_norms();

static constexpr int T = 256;          // threads per block
static constexpr int STAGE_F = 80;     // floats/point staged (l=1..8)

extern __shared__ float buf[];         // T * STAGE_F floats = 80 KB
                                       // segment l at float offset T*(l*l-1)

__global__ __launch_bounds__(T)
void sph_l8_pipe_kernel(const float* __restrict__ R, float* __restrict__ out, int N) {
    const int tid = threadIdx.x;
    const int blockStart = blockIdx.x * T;
    const int i = blockStart + tid;
    const int valid = min(T, N - blockStart);

    float x, y, z;
    if (i < N) {
        x = R[3 * i + 0];
        y = R[3 * i + 1];
        z = R[3 * i + 2];
        float inv = rsqrtf(fmaf(x, x, fmaf(y, y, z * z)));
        x *= inv; y *= inv; z *= inv;
    } else {
        x = 0.0f; y = 0.0f; z = 1.0f;
    }

    // A[m] + i B[m] = (x + i y)^m
    float A[9], B[9], p1[9], p2[9];
    A[0] = 1.0f; B[0] = 0.0f;
#pragma unroll
    for (int m = 1; m <= 8; ++m) {
        A[m] = x * A[m - 1] - y * B[m - 1];
        B[m] = x * B[m - 1] + y * A[m - 1];
    }
    constexpr float PMM[9] = {1.f, 1.f, 3.f, 15.f, 105.f, 945.f,
                              10395.f, 135135.f, 2027025.f};

    // l = 0: direct, stride-1
    if (i < N) out[i] = g_norm.v[0];
    p2[0] = 0.0f; p1[0] = PMM[0];

    // ============ PHASE 1: compute + stage l = 1..5 ============
#pragma unroll
    for (int l = 1; l <= 5; ++l) {
        const int W = 2 * l + 1;
        float* row = buf + T * (l * l - 1) + tid * W;
#pragma unroll
        for (int m = 0; m <= l; ++m) {
            float p;
            if (l == m) {
                p = PMM[m];
                p2[m] = 0.0f;
            } else if (l == m + 1) {
                p = (float)(2 * m + 1) * z * p1[m];
                p2[m] = p1[m];
            } else {
                p = ((float)(2 * l - 1) * z * p1[m] - (float)(l + m - 1) * p2[m])
                    * (1.0f / (float)(l - m));
                p2[m] = p1[m];
            }
            p1[m] = p;
            const float c = g_norm.v[l * (l + 1) / 2 + m];
            if (m == 0) {
                row[l] = c * p;
            } else {
                row[l + m] = c * p * A[m];
                row[l - m] = c * p * B[m];
            }
        }
    }
    __syncthreads();

    // issue copies for l = 5..1 (largest first); stores drain asynchronously
#pragma unroll
    for (int k = 0; k < 5; ++k) {
        const int l = 5 - k;
        const int W = 2 * l + 1;
        float* dst = out + (size_t)N * (size_t)(l * l)
                         + (size_t)blockStart * (size_t)W;
        const float* src = buf + T * (l * l - 1);
        if (valid == T) {
            float4* __restrict__ d4 = (float4*)dst;
            const float4* __restrict__ s4 = (const float4*)src;
            const int n4 = (T * W) >> 2;                 // 64*W
#pragma unroll
            for (int j = tid; j < n4; j += T) __stcs(&d4[j], s4[j]);
        } else {
            const int nf = valid * W;
            for (int j = tid; j < nf; j += T) dst[j] = src[j];
        }
    }

    // ============ PHASE 2: compute + stage l = 6..8 (disjoint region) ============
#pragma unroll
    for (int l = 6; l <= 8; ++l) {
        const int W = 2 * l + 1;
        float* row = buf + T * (l * l - 1) + tid * W;
#pragma unroll
        for (int m = 0; m <= l; ++m) {
            float p;
            if (l == m) {
                p = PMM[m];
                p2[m] = 0.0f;
            } else if (l == m + 1) {
                p = (float)(2 * m + 1) * z * p1[m];
                p2[m] = p1[m];
            } else {
                p = ((float)(2 * l - 1) * z * p1[m] - (float)(l + m - 1) * p2[m])
                    * (1.0f / (float)(l - m));
                p2[m] = p1[m];
            }
            p1[m] = p;
            const float c = g_norm.v[l * (l + 1) / 2 + m];
            if (m == 0) {
                row[l] = c * p;
            } else {
                row[l + m] = c * p * A[m];
                row[l - m] = c * p * B[m];
            }
        }
    }
    __syncthreads();

#pragma unroll
    for (int k = 0; k < 3; ++k) {
        const int l = 8 - k;               // 8,7,6
        const int W = 2 * l + 1;
        float* dst = out + (size_t)N * (size_t)(l * l)
                         + (size_t)blockStart * (size_t)W;
        const float* src = buf + T * (l * l - 1);
        if (valid == T) {
            float4* __restrict__ d4 = (float4*)dst;
            const float4* __restrict__ s4 = (const float4*)src;
            const int n4 = (T * W) >> 2;
#pragma unroll
            for (int j = tid; j < n4; j += T) __stcs(&d4[j], s4[j]);
        } else {
            const int nf = valid * W;
            for (int j = tid; j < nf; j += T) dst[j] = src[j];
        }
    }
}

extern "C" void kernel_launch(void* const* d_in, const int* in_sizes, int n_in,
                              void* d_out, int out_size) {
    const float* R = (const float*)d_in[0];
    float* out = (float*)d_out;
    int N = in_sizes[0] / 3;
    int blocks = (N + T - 1) / T;
    size_t smem = (size_t)T * STAGE_F * sizeof(float);   // 81920 B
    cudaFuncSetAttribute(sph_l8_pipe_kernel,
                         cudaFuncAttributeMaxDynamicSharedMemorySize, (int)smem);
    sph_l8_pipe_kernel<<<blocks, T, smem>>>(R, out, N);
}

// round 11
// speedup vs baseline: 1.5590x; 1.5590x over previous
#include <cuda_runtime.h>
#include <stdint.h>

// Real spherical harmonics up to L=8. Output = concat of 9 parts; part l at
// element offset N*l*l, row i at i*(2l+1), column (l+m), m=-l..l.
//
// Final configuration (best measured: 48.64 us, ~6.9 TB/s effective):
//   T=256, single-barrier full staging of l=1..8 in 80 KB dynamic smem
//   (2 CTA/SM -> cross-CTA compute/store phase overlap), copy phase is
//   8 coalesced float4 __stcs loops, largest segment first (4..17 KB
//   contiguous DRAM runs per segment per block). l=0 stored direct.

static constexpr double PI_D = 3.141592653589793238462643383279502884;

constexpr double csqrt(double x) {
    double g = (x > 1.0) ? x : 1.0;
    for (int i = 0; i < 200; ++i) g = 0.5 * (g + x / g);
    return g;
}
constexpr double cfact(int n) {
    double r = 1.0;
    for (int i = 2; i <= n; ++i) r *= (double)i;
    return r;
}

struct NormTab { float v[45]; };
constexpr NormTab make_norms() {
    NormTab t{};
    for (int l = 0; l <= 8; ++l)
        for (int m = 0; m <= l; ++m) {
            double n = csqrt((2.0 * l + 1.0) / (4.0 * PI_D) * cfact(l - m) / cfact(l + m));
            if (m > 0) n *= csqrt(2.0);
            t.v[l * (l + 1) / 2 + m] = (float)n;
        }
    return t;
}
__constant__ NormTab g_norm = make_norms();

static constexpr int T = 256;          // threads per block
static constexpr int STAGE_F = 80;     // floats/point staged (l=1..8)

extern __shared__ float buf[];         // T * STAGE_F floats = 80 KB

__global__ __launch_bounds__(T)
void sph_l8_final_kernel(const float* __restrict__ R, float* __restrict__ out, int N) {
    const int tid = threadIdx.x;
    const int blockStart = blockIdx.x * T;
    const int i = blockStart + tid;
    const int valid = min(T, N - blockStart);

    float x, y, z;
    if (i < N) {
        x = R[3 * i + 0];
        y = R[3 * i + 1];
        z = R[3 * i + 2];
        float inv = rsqrtf(fmaf(x, x, fmaf(y, y, z * z)));
        x *= inv; y *= inv; z *= inv;
    } else {
        x = 0.0f; y = 0.0f; z = 1.0f;
    }

    // A[m] + i B[m] = (x + i y)^m
    float A[9], B[9], p1[9], p2[9];
    A[0] = 1.0f; B[0] = 0.0f;
#pragma unroll
    for (int m = 1; m <= 8; ++m) {
        A[m] = x * A[m - 1] - y * B[m - 1];
        B[m] = x * B[m - 1] + y * A[m - 1];
    }
    constexpr float PMM[9] = {1.f, 1.f, 3.f, 15.f, 105.f, 945.f,
                              10395.f, 135135.f, 2027025.f};

    // l = 0: direct, stride-1
    if (i < N) out[i] = g_norm.v[0];
    p2[0] = 0.0f; p1[0] = PMM[0];

    // ---- compute + stage l = 1..8 (segment l at float offset T*(l*l-1)) ----
#pragma unroll
    for (int l = 1; l <= 8; ++l) {
        const int W = 2 * l + 1;
        float* row = buf + T * (l * l - 1) + tid * W;
#pragma unroll
        for (int m = 0; m <= l; ++m) {
            float p;
            if (l == m) {
                p = PMM[m];
                p2[m] = 0.0f;
            } else if (l == m + 1) {
                p = (float)(2 * m + 1) * z * p1[m];
                p2[m] = p1[m];
            } else {
                p = ((float)(2 * l - 1) * z * p1[m] - (float)(l + m - 1) * p2[m])
                    * (1.0f / (float)(l - m));
                p2[m] = p1[m];
            }
            p1[m] = p;
            const float c = g_norm.v[l * (l + 1) / 2 + m];
            if (m == 0) {
                row[l] = c * p;
            } else {
                row[l + m] = c * p * A[m];
                row[l - m] = c * p * B[m];
            }
        }
    }
    __syncthreads();

    // ---- copy phase: largest segments first, no barriers in between ----
#pragma unroll
    for (int k = 0; k < 8; ++k) {
        const int l = 8 - k;               // 8,7,...,1
        const int W = 2 * l + 1;
        float* dst = out + (size_t)N * (size_t)(l * l)
                         + (size_t)blockStart * (size_t)W;
        const float* src = buf + T * (l * l - 1);
        if (valid == T) {
            float4* __restrict__ d4 = (float4*)dst;       // 16B-aligned
            const float4* __restrict__ s4 = (const float4*)src;
            const int n4 = (T * W) >> 2;                  // 64*W
#pragma unroll
            for (int j = tid; j < n4; j += T) __stcs(&d4[j], s4[j]);
        } else {
            const int nf = valid * W;
            for (int j = tid; j < nf; j += T) dst[j] = src[j];
        }
    }
}

extern "C" void kernel_launch(void* const* d_in, const int* in_sizes, int n_in,
                              void* d_out, int out_size) {
    const float* R = (const float*)d_in[0];
    float* out = (float*)d_out;
    int N = in_sizes[0] / 3;
    int blocks = (N + T - 1) / T;
    size_t smem = (size_t)T * STAGE_F * sizeof(float);   // 81920 B
    cudaFuncSetAttribute(sph_l8_final_kernel,
                         cudaFuncAttributeMaxDynamicSharedMemorySize, (int)smem);
    sph_l8_final_kernel<<<blocks, T, smem>>>(R, out, N);
}

// round 12
// speedup vs baseline: 1.5641x; 1.0033x over previous
#include <cuda_runtime.h>
#include <stdint.h>

// Real spherical harmonics up to L=8. Output = concat of 9 parts; part l at
// element offset N*l*l, row i at i*(2l+1), column (l+m), m=-l..l.
//
// T=192, single-barrier full staging of l=1..8 in 60 KB dynamic smem
// -> 3 CTAs/SM for finer-grained cross-CTA compute/store phase
// interleaving (R9 showed this overlap is the binding resource).
// Copy phase: 8 coalesced float4 __stcs loops, largest segment first.
// l=0 stored direct (stride-1).

static constexpr double PI_D = 3.141592653589793238462643383279502884;

constexpr double csqrt(double x) {
    double g = (x > 1.0) ? x : 1.0;
    for (int i = 0; i < 200; ++i) g = 0.5 * (g + x / g);
    return g;
}
constexpr double cfact(int n) {
    double r = 1.0;
    for (int i = 2; i <= n; ++i) r *= (double)i;
    return r;
}

struct NormTab { float v[45]; };
constexpr NormTab make_norms() {
    NormTab t{};
    for (int l = 0; l <= 8; ++l)
        for (int m = 0; m <= l; ++m) {
            double n = csqrt((2.0 * l + 1.0) / (4.0 * PI_D) * cfact(l - m) / cfact(l + m));
            if (m > 0) n *= csqrt(2.0);
            t.v[l * (l + 1) / 2 + m] = (float)n;
        }
    return t;
}
__constant__ NormTab g_norm = make_norms();

static constexpr int T = 192;          // threads per block -> 60 KB smem, 3 CTA/SM
static constexpr int STAGE_F = 80;     // floats/point staged (l=1..8)

extern __shared__ float buf[];         // T * STAGE_F floats = 61440 B

__global__ __launch_bounds__(T)
void sph_l8_t192_kernel(const float* __restrict__ R, float* __restrict__ out, int N) {
    const int tid = threadIdx.x;
    const int blockStart = blockIdx.x * T;
    const int i = blockStart + tid;
    const int valid = min(T, N - blockStart);

    float x, y, z;
    if (i < N) {
        x = R[3 * i + 0];
        y = R[3 * i + 1];
        z = R[3 * i + 2];
        float inv = rsqrtf(fmaf(x, x, fmaf(y, y, z * z)));
        x *= inv; y *= inv; z *= inv;
    } else {
        x = 0.0f; y = 0.0f; z = 1.0f;
    }

    // A[m] + i B[m] = (x + i y)^m
    float A[9], B[9], p1[9], p2[9];
    A[0] = 1.0f; B[0] = 0.0f;
#pragma unroll
    for (int m = 1; m <= 8; ++m) {
        A[m] = x * A[m - 1] - y * B[m - 1];
        B[m] = x * B[m - 1] + y * A[m - 1];
    }
    constexpr float PMM[9] = {1.f, 1.f, 3.f, 15.f, 105.f, 945.f,
                              10395.f, 135135.f, 2027025.f};

    // l = 0: direct, stride-1
    if (i < N) out[i] = g_norm.v[0];
    p2[0] = 0.0f; p1[0] = PMM[0];

    // ---- compute + stage l = 1..8 (segment l at float offset T*(l*l-1)) ----
#pragma unroll
    for (int l = 1; l <= 8; ++l) {
        const int W = 2 * l + 1;
        float* row = buf + T * (l * l - 1) + tid * W;
#pragma unroll
        for (int m = 0; m <= l; ++m) {
            float p;
            if (l == m) {
                p = PMM[m];
                p2[m] = 0.0f;
            } else if (l == m + 1) {
                p = (float)(2 * m + 1) * z * p1[m];
                p2[m] = p1[m];
            } else {
                p = ((float)(2 * l - 1) * z * p1[m] - (float)(l + m - 1) * p2[m])
                    * (1.0f / (float)(l - m));
                p2[m] = p1[m];
            }
            p1[m] = p;
            const float c = g_norm.v[l * (l + 1) / 2 + m];
            if (m == 0) {
                row[l] = c * p;
            } else {
                row[l + m] = c * p * A[m];
                row[l - m] = c * p * B[m];
            }
        }
    }
    __syncthreads();

    // ---- copy phase: largest segments first, no barriers in between ----
#pragma unroll
    for (int k = 0; k < 8; ++k) {
        const int l = 8 - k;               // 8,7,...,1
        const int W = 2 * l + 1;
        float* dst = out + (size_t)N * (size_t)(l * l)
                         + (size_t)blockStart * (size_t)W;
        const float* src = buf + T * (l * l - 1);
        if (valid == T) {
            float4* __restrict__ d4 = (float4*)dst;       // 16B-aligned: 4*N*l*l, 768*W
            const float4* __restrict__ s4 = (const float4*)src;
            const int n4 = (T * W) >> 2;                  // 48*W
#pragma unroll
            for (int j = tid; j < n4; j += T) __stcs(&d4[j], s4[j]);
        } else {
            const int nf = valid * W;
            for (int j = tid; j < nf; j += T) dst[j] = src[j];
        }
    }
}

extern "C" void kernel_launch(void* const* d_in, const int* in_sizes, int n_in,
                              void* d_out, int out_size) {
    const float* R = (const float*)d_in[0];
    float* out = (float*)d_out;
    int N = in_sizes[0] / 3;
    int blocks = (N + T - 1) / T;
    size_t smem = (size_t)T * STAGE_F * sizeof(float);   // 61440 B
    cudaFuncSetAttribute(sph_l8_t192_kernel,
                         cudaFuncAttributeMaxDynamicSharedMemorySize, (int)smem);
    sph_l8_t192_kernel<<<blocks, T, smem>>>(R, out, N);
}